// round 1
// baseline (speedup 1.0000x reference)
#include <cuda_runtime.h>

namespace {
constexpr int kB = 128, kS = 2048, kD = 128, kNQ = 18;
constexpr int TS = 128;                 // s-tile size
constexpr int NTILE = kS / TS;          // 16
constexpr int THREADS = 256;
constexpr float SCALE = 0.08838834764831845f;  // 1/sqrt(128)

constexpr int XBUF_F4 = TS * 32;                 // float4 per x buffer
constexpr int SMEM_X = 2 * XBUF_F4 * 16;         // 131072 B (double buffer)
constexpr int SMEM_Q = kNQ * kD * 4;             // 9216 B
constexpr int SMEM_P = kNQ * TS * 4;             // 9216 B
constexpr int SMEM_BYTES = SMEM_X + SMEM_Q + SMEM_P + 128;
}

// ---- packed f32x2 helpers (B300 FFMA2 path, only reachable via PTX) ----
__device__ __forceinline__ unsigned long long pk2(float a, float b) {
    unsigned long long r;
    asm("mov.b64 %0, {%1,%2};" : "=l"(r) : "f"(a), "f"(b));
    return r;
}
__device__ __forceinline__ unsigned long long f2ma(unsigned long long a,
                                                   unsigned long long b,
                                                   unsigned long long c) {
    unsigned long long d;
    asm("fma.rn.f32x2 %0, %1, %2, %3;" : "=l"(d) : "l"(a), "l"(b), "l"(c));
    return d;
}
__device__ __forceinline__ float2 up2(unsigned long long v) {
    float lo, hi;
    asm("mov.b64 {%0,%1}, %2;" : "=f"(lo), "=f"(hi) : "l"(v));
    return make_float2(lo, hi);
}
__device__ __forceinline__ void cpa16(void* dst, const void* src) {
    unsigned a = (unsigned)__cvta_generic_to_shared(dst);
    asm volatile("cp.async.cg.shared.global [%0], [%1], 16;" :: "r"(a), "l"(src));
}

__global__ void __launch_bounds__(THREADS, 1)
AttentionPooling_24378234372356_kernel(const float* __restrict__ x,
                                       const float* __restrict__ qe,
                                       const int*   __restrict__ ques,
                                       const int*   __restrict__ mask,
                                       float*       __restrict__ out)
{
    extern __shared__ char smem[];
    float4* xb4  = reinterpret_cast<float4*>(smem);
    float*  q_sm = reinterpret_cast<float*>(smem + SMEM_X);
    float*  p_sm = q_sm + kNQ * kD;
    float*  l_sm = p_sm + kNQ * TS;

    const int t = threadIdx.x;
    const int b = blockIdx.x;

    // ---- gather question embeddings, pre-scaled by 1/sqrt(D) ----
    for (int i = t; i < kNQ * 32; i += THREADS) {
        int j = i >> 5, d4 = i & 31;
        int qi = ques[b * kNQ + j];
        float4 v = reinterpret_cast<const float4*>(qe + qi * kD)[d4];
        v.x *= SCALE; v.y *= SCALE; v.z *= SCALE; v.w *= SCALE;
        reinterpret_cast<float4*>(q_sm)[j * 32 + d4] = v;
    }
    if (t < kNQ) l_sm[t] = 0.0f;

    const float* xb = x + (size_t)b * kS * kD;
    const int*   mb = mask + b * kS;

    // tile loader: swizzled store col' = (d4 + s) & 31 -> conflict-free in
    // both row-major (phase A) and column-major (phase B) read patterns.
    auto load_tile = [&](int tile, int buf) {
        const float* src = xb + tile * TS * kD;
        float4* dst = xb4 + buf * XBUF_F4;
        #pragma unroll
        for (int k = 0; k < 16; ++k) {
            int i = t + k * THREADS;
            int s = i >> 5, d4 = i & 31;
            cpa16(&dst[s * 32 + ((d4 + s) & 31)], src + s * kD + d4 * 4);
        }
        asm volatile("cp.async.commit_group;");
    };

    load_tile(0, 0);

    // output accumulators: ALL 18 queries x one float4 of d, per (d4, s-slice)
    unsigned long long acc[kNQ][2];
    #pragma unroll
    for (int j = 0; j < kNQ; ++j) { acc[j][0] = 0ull; acc[j][1] = 0ull; }

    const int sA  = t & (TS - 1);   // phase A: s index
    const int qb  = (t >> 7) * 9;   // phase A: query group base (0 or 9)
    const int d4B = t & 31;         // phase B: float4 column
    const int rB  = t >> 5;         // phase B: s-slice (0..7)

    for (int tile = 0; tile < NTILE; ++tile) {
        const int buf = tile & 1;
        if (tile + 1 < NTILE) {
            load_tile(tile + 1, buf ^ 1);
            asm volatile("cp.async.wait_group 1;");
        } else {
            asm volatile("cp.async.wait_group 0;");
        }
        __syncthreads();

        // ---- phase A: scores for 9 queries at s = sA ----
        {
            const ulonglong2* xt =
                reinterpret_cast<const ulonglong2*>(xb4 + buf * XBUF_F4 + sA * 32);
            const ulonglong2* qt = reinterpret_cast<const ulonglong2*>(q_sm);
            unsigned long long sc[9];
            #pragma unroll
            for (int j = 0; j < 9; ++j) sc[j] = 0ull;
            #pragma unroll 8
            for (int d4 = 0; d4 < 32; ++d4) {
                ulonglong2 xv = xt[(d4 + sA) & 31];
                #pragma unroll
                for (int j = 0; j < 9; ++j) {
                    ulonglong2 qv = qt[(qb + j) * 32 + d4];
                    sc[j] = f2ma(xv.x, qv.x, sc[j]);
                    sc[j] = f2ma(xv.y, qv.y, sc[j]);
                }
            }
            const int mk = mb[tile * TS + sA];
            #pragma unroll
            for (int j = 0; j < 9; ++j) {
                float2 f = up2(sc[j]);
                float pv = mk ? __expf(f.x + f.y) : 0.0f;   // logits bounded; no max-sub needed
                p_sm[(qb + j) * TS + sA] = pv;
            }
        }
        __syncthreads();

        // ---- row-sums of p into l (144 threads, smem atomics) ----
        if (t < kNQ * 8) {
            int q = t >> 3, w = t & 7;
            const float4* pr = reinterpret_cast<const float4*>(p_sm + q * TS + w * 16);
            float ss = 0.0f;
            #pragma unroll
            for (int k2 = 0; k2 < 4; ++k2) {
                float4 v = pr[k2];
                ss += (v.x + v.y) + (v.z + v.w);
            }
            atomicAdd(&l_sm[q], ss);
        }

        // ---- phase B: acc[q][4d] += p[q][s] * x[s][4d] over s in this slice ----
        {
            const ulonglong2* xt =
                reinterpret_cast<const ulonglong2*>(xb4 + buf * XBUF_F4);
            #pragma unroll 2
            for (int i = 0; i < 4; ++i) {
                const int s0 = rB * 16 + i * 4;
                ulonglong2 xq[4];
                #pragma unroll
                for (int k2 = 0; k2 < 4; ++k2)
                    xq[k2] = xt[(s0 + k2) * 32 + ((d4B + s0 + k2) & 31)];
                #pragma unroll
                for (int j = 0; j < kNQ; ++j) {
                    float4 pv =
                        reinterpret_cast<const float4*>(p_sm + j * TS)[rB * 4 + i];
                    unsigned long long p0 = pk2(pv.x, pv.x);
                    acc[j][0] = f2ma(xq[0].x, p0, acc[j][0]);
                    acc[j][1] = f2ma(xq[0].y, p0, acc[j][1]);
                    unsigned long long p1 = pk2(pv.y, pv.y);
                    acc[j][0] = f2ma(xq[1].x, p1, acc[j][0]);
                    acc[j][1] = f2ma(xq[1].y, p1, acc[j][1]);
                    unsigned long long p2 = pk2(pv.z, pv.z);
                    acc[j][0] = f2ma(xq[2].x, p2, acc[j][0]);
                    acc[j][1] = f2ma(xq[2].y, p2, acc[j][1]);
                    unsigned long long p3 = pk2(pv.w, pv.w);
                    acc[j][0] = f2ma(xq[3].x, p3, acc[j][0]);
                    acc[j][1] = f2ma(xq[3].y, p3, acc[j][1]);
                }
            }
        }
        __syncthreads();
    }

    // ---- reduce 8 s-slices through smem (reuse x buffers), normalize, store ----
    float* red = reinterpret_cast<float*>(smem);   // needs 8*18*128*4 = 73728 B
    #pragma unroll
    for (int j = 0; j < kNQ; ++j) {
        float2 a = up2(acc[j][0]);
        float2 c = up2(acc[j][1]);
        reinterpret_cast<float4*>(red)[(rB * kNQ + j) * 32 + d4B] =
            make_float4(a.x, a.y, c.x, c.y);
    }
    __syncthreads();
    float* ob = out + (size_t)b * kNQ * kD;
    for (int o = t; o < kNQ * kD; o += THREADS) {
        int q = o >> 7;
        float ssum = 0.0f;
        #pragma unroll
        for (int r = 0; r < 8; ++r) ssum += red[r * (kNQ * kD) + o];
        ob[o] = ssum / l_sm[q];
    }
}

extern "C" void kernel_launch(void* const* d_in, const int* in_sizes, int n_in,
                              void* d_out, int out_size) {
    const float* x    = (const float*)d_in[0];
    const float* qe   = (const float*)d_in[1];
    const int*   ques = (const int*)d_in[2];
    const int*   mask = (const int*)d_in[3];
    float* out = (float*)d_out;

    cudaFuncSetAttribute(AttentionPooling_24378234372356_kernel,
                         cudaFuncAttributeMaxDynamicSharedMemorySize, SMEM_BYTES);
    AttentionPooling_24378234372356_kernel<<<kB, THREADS, SMEM_BYTES>>>(
        x, qe, ques, mask, out);
}